// round 1
// baseline (speedup 1.0000x reference)
#include <cuda_runtime.h>
#include <math.h>

#define EPSV 1e-4f
#define NB   16      // batch
#define HP   14      // feature map side
#define NP   196     // patches per image
#define TP   3136    // total patches
#define PT   8       // patches per block
#define NBLK (TP/PT) // 392
#define PROTO 60

// scratch (allocation-free: device globals)
__device__ float g_dist[NB*PROTO*NP];
__device__ float g_act [NB*PROTO*NP];
__device__ float g_pact[NB*PROTO];

// ---------------------------------------------------------------------------
// K1: fused patch-conv + MLP + prototype distances. One block = PT patches.
// smem stages: in[PT][768] -> f[PT][512] -> h1[PT][256] -> h2[PT][256]
//              -> h3[PT][128] -> h4[PT][128] (buffers reused A->B->C->A->B->C)
// ---------------------------------------------------------------------------
__global__ __launch_bounds__(256) void k_mlp(
    const float* __restrict__ x,
    const float* __restrict__ Wf, const float* __restrict__ bf,
    const float* __restrict__ W1, const float* __restrict__ b1,
    const float* __restrict__ W2, const float* __restrict__ b2,
    const float* __restrict__ W3, const float* __restrict__ b3,
    const float* __restrict__ W4, const float* __restrict__ b4,
    const float* __restrict__ prot)
{
    extern __shared__ float sm[];
    float* sA = sm;            // PT*768 floats (24KB); reused as h2 PT*256
    float* sB = sm + PT*768;   // PT*512 (16KB);        reused as h3/h4 src
    float* sC = sB + PT*512;   // PT*256 (8KB);         reused as h4 out

    const int tid = threadIdx.x;
    const int gp0 = blockIdx.x * PT;

    // ---- load PT patches of input (3x16x16 each) into sA, layout matches Wf rows
    for (int e = tid; e < PT*768; e += 256) {
        int pt = e / 768, k = e - pt*768;
        int c = k >> 8, r = (k >> 4) & 15, col = k & 15;
        int gp = gp0 + pt;
        int b = gp / NP, hw = gp - b*NP;
        int py = hw / HP, px = hw - py*HP;
        sA[e] = x[((b*3 + c)*224 + py*16 + r)*224 + px*16 + col];
    }
    __syncthreads();

    // ---- stage 0: patch conv, 512 outputs (2 per thread), K=768 -> sB
    {
        float acc0[PT], acc1[PT];
        #pragma unroll
        for (int pt = 0; pt < PT; pt++) { acc0[pt] = 0.f; acc1[pt] = 0.f; }
        const int o0 = tid, o1 = tid + 256;
        const float* w0p = Wf + (size_t)o0 * 768;
        const float* w1p = Wf + (size_t)o1 * 768;
        #pragma unroll 4
        for (int k = 0; k < 768; k++) {
            float w0 = w0p[k], w1 = w1p[k];
            #pragma unroll
            for (int pt = 0; pt < PT; pt++) {
                float a = sA[pt*768 + k];
                acc0[pt] = fmaf(w0, a, acc0[pt]);
                acc1[pt] = fmaf(w1, a, acc1[pt]);
            }
        }
        float bb0 = bf[o0], bb1 = bf[o1];
        #pragma unroll
        for (int pt = 0; pt < PT; pt++) {
            sB[pt*512 + o0] = fmaxf(acc0[pt] + bb0, 0.f);
            sB[pt*512 + o1] = fmaxf(acc1[pt] + bb1, 0.f);
        }
    }
    __syncthreads();

    // ---- stage 1: 256 outputs, K=512 : sB -> sC
    {
        float acc[PT];
        #pragma unroll
        for (int pt = 0; pt < PT; pt++) acc[pt] = 0.f;
        const float* wp = W1 + (size_t)tid * 512;
        #pragma unroll 4
        for (int k = 0; k < 512; k++) {
            float w = wp[k];
            #pragma unroll
            for (int pt = 0; pt < PT; pt++)
                acc[pt] = fmaf(w, sB[pt*512 + k], acc[pt]);
        }
        float bb = b1[tid];
        #pragma unroll
        for (int pt = 0; pt < PT; pt++)
            sC[pt*256 + tid] = fmaxf(acc[pt] + bb, 0.f);
    }
    __syncthreads();

    // ---- stage 2: 256 outputs, K=256 : sC -> sA (reuse)
    {
        float acc[PT];
        #pragma unroll
        for (int pt = 0; pt < PT; pt++) acc[pt] = 0.f;
        const float* wp = W2 + (size_t)tid * 256;
        #pragma unroll 4
        for (int k = 0; k < 256; k++) {
            float w = wp[k];
            #pragma unroll
            for (int pt = 0; pt < PT; pt++)
                acc[pt] = fmaf(w, sC[pt*256 + k], acc[pt]);
        }
        float bb = b2[tid];
        #pragma unroll
        for (int pt = 0; pt < PT; pt++)
            sA[pt*256 + tid] = fmaxf(acc[pt] + bb, 0.f);
    }
    __syncthreads();

    // ---- stage 3: 128 outputs, K=256 : sA -> sB (each thread: 1 out x 4 patches)
    {
        const int o = tid & 127;
        const int half = tid >> 7;          // 0 or 1 -> patch group
        float acc[4] = {0.f, 0.f, 0.f, 0.f};
        const float* wp = W3 + (size_t)o * 256;
        #pragma unroll 4
        for (int k = 0; k < 256; k++) {
            float w = wp[k];
            #pragma unroll
            for (int j = 0; j < 4; j++)
                acc[j] = fmaf(w, sA[(half*4 + j)*256 + k], acc[j]);
        }
        float bb = b3[o];
        #pragma unroll
        for (int j = 0; j < 4; j++)
            sB[(half*4 + j)*128 + o] = fmaxf(acc[j] + bb, 0.f);
    }
    __syncthreads();

    // ---- stage 4: 128 outputs, K=128, sigmoid : sB -> sC
    {
        const int o = tid & 127;
        const int half = tid >> 7;
        float acc[4] = {0.f, 0.f, 0.f, 0.f};
        const float* wp = W4 + (size_t)o * 128;
        #pragma unroll 4
        for (int k = 0; k < 128; k++) {
            float w = wp[k];
            #pragma unroll
            for (int j = 0; j < 4; j++)
                acc[j] = fmaf(w, sB[(half*4 + j)*128 + k], acc[j]);
        }
        float bb = b4[o];
        #pragma unroll
        for (int j = 0; j < 4; j++) {
            float z = acc[j] + bb;
            sC[(half*4 + j)*128 + o] = 1.0f / (1.0f + expf(-z));
        }
    }
    __syncthreads();

    // ---- prototype distances + activation: 60 protos x PT patches
    for (int q = tid; q < PROTO*PT; q += 256) {
        int p  = q / PT, pt = q - p*PT;
        const float* pr = prot + p*128;
        const float* hh = sC + pt*128;
        float acc = 0.f;
        #pragma unroll 4
        for (int k = 0; k < 128; k++) {
            float df = hh[k] - pr[k];
            acc = fmaf(df, df, acc);
        }
        float d = sqrtf(acc);
        float a = logf((d + 1.0f) / (d + EPSV));
        int gp = gp0 + pt;
        int b = gp / NP, hw = gp - b*NP;
        int idx = (b*PROTO + p)*NP + hw;
        g_dist[idx] = d;
        g_act[idx]  = a;
    }
}

// ---------------------------------------------------------------------------
// K2: per-(b,p) top-k smallest distances (act is monotone-decreasing in d, so
// the same 5 indices give top-k act). One warp per task, iterative min-extract.
// ---------------------------------------------------------------------------
__global__ void k_topk(const int* __restrict__ kptr, float* __restrict__ out_mind)
{
    const int k = *kptr;
    const int warp = (blockIdx.x * blockDim.x + threadIdx.x) >> 5;
    const int lane = threadIdx.x & 31;
    if (warp >= NB*PROTO) return;

    const float* dp = g_dist + warp*NP;
    float v[7];
    #pragma unroll
    for (int j = 0; j < 7; j++) {
        int i = lane + 32*j;
        v[j] = (i < NP) ? dp[i] : 1e30f;
    }

    float sd = 0.f, sa = 0.f;
    for (int it = 0; it < k; it++) {
        float m = v[0]; int mj = 0;
        #pragma unroll
        for (int j = 1; j < 7; j++) if (v[j] < m) { m = v[j]; mj = j; }
        float bm = m; int bidx = (mj << 5) | lane;
        #pragma unroll
        for (int off = 16; off; off >>= 1) {
            float om = __shfl_xor_sync(0xffffffffu, bm, off);
            int   oi = __shfl_xor_sync(0xffffffffu, bidx, off);
            if (om < bm || (om == bm && oi < bidx)) { bm = om; bidx = oi; }
        }
        sd += bm;
        sa += logf((bm + 1.0f) / (bm + EPSV));
        if (lane == (bidx & 31)) v[bidx >> 5] = 1e30f;
    }
    if (lane == 0) {
        out_mind[warp] = sd / (float)k;
        g_pact[warp]   = sa / (float)k;
    }
}

// ---------------------------------------------------------------------------
// K3: logits[b][c] = sum_p proto_act[b][p] * last_W[c][p]   (16x3 outputs)
// ---------------------------------------------------------------------------
__global__ void k_logits(const float* __restrict__ lastW, float* __restrict__ out)
{
    int t = threadIdx.x;
    if (t < NB*3) {
        int b = t / 3, c = t - b*3;
        float s = 0.f;
        #pragma unroll 4
        for (int p = 0; p < PROTO; p++)
            s += g_pact[b*PROTO + p] * lastW[c*PROTO + p];
        out[t] = s;
    }
}

// ---------------------------------------------------------------------------
// K4: 16x nearest upsample of act -> 192.7 MB of stores. Each thread writes
// one full 16-float run (4 x float4) from a single act value.
// ---------------------------------------------------------------------------
__global__ __launch_bounds__(256) void k_ups(float* __restrict__ out)
{
    int i = blockIdx.x * blockDim.x + threadIdx.x;  // [0, NB*PROTO*224*14)
    int xr = i % 14;
    int t2 = i / 14;
    int y  = t2 % 224;
    int bp = t2 / 224;
    float v = g_act[bp*NP + (y >> 4)*HP + xr];
    float4 vv = make_float4(v, v, v, v);
    float4* o = (float4*)(out + ((size_t)(bp*224 + y)*224 + xr*16));
    o[0] = vv; o[1] = vv; o[2] = vv; o[3] = vv;
}

// ---------------------------------------------------------------------------
extern "C" void kernel_launch(void* const* d_in, const int* in_sizes, int n_in,
                              void* d_out, int out_size)
{
    const float* x    = (const float*)d_in[0];
    // d_in[1] = mascaras (unused by reference)
    const float* Wf   = (const float*)d_in[2];
    const float* bf   = (const float*)d_in[3];
    const float* W1   = (const float*)d_in[4];
    const float* b1   = (const float*)d_in[5];
    const float* W2   = (const float*)d_in[6];
    const float* b2   = (const float*)d_in[7];
    const float* W3   = (const float*)d_in[8];
    const float* b3   = (const float*)d_in[9];
    const float* W4   = (const float*)d_in[10];
    const float* b4   = (const float*)d_in[11];
    const float* prot = (const float*)d_in[12];
    const float* lastW= (const float*)d_in[13];
    const int*   kptr = (const int*)d_in[14];
    float* out = (float*)d_out;

    // output packing: logits[48] | min_distances[960] | upsampled[16*60*224*224]
    const int SMEM = PT*768*4 + PT*512*4 + PT*256*4;  // 49152 bytes
    cudaFuncSetAttribute(k_mlp, cudaFuncAttributeMaxDynamicSharedMemorySize, 64*1024);

    k_mlp<<<NBLK, 256, SMEM>>>(x, Wf, bf, W1, b1, W2, b2, W3, b3, W4, b4, prot);
    k_topk<<<(NB*PROTO*32 + 255)/256, 256>>>(kptr, out + 48);
    k_logits<<<1, 64>>>(lastW, out);
    k_ups<<<(NB*PROTO*224*14)/256, 256>>>(out + 48 + NB*PROTO);
}

// round 2
// speedup vs baseline: 4.8722x; 4.8722x over previous
#include <cuda_runtime.h>
#include <math.h>

#define EPSV 1e-4f
#define NB   16      // batch
#define HP   14      // feature map side
#define NP   196     // patches per image
#define TP   3136    // total patches
#define PT   8       // patches per block
#define NBLK (TP/PT) // 392
#define PROTO 60

// scratch (allocation-free: device globals)
__device__ float g_dist[NB*PROTO*NP];
__device__ float g_act [NB*PROTO*NP];
__device__ float g_pact[NB*PROTO];

// transposed weights: Wt[k][o] so per-k loads are coalesced across threads
__device__ float g_Wft[768*512];
__device__ float g_W1t[512*256];
__device__ float g_W2t[256*256];
__device__ float g_W3t[256*128];
__device__ float g_W4t[128*128];

#define S_WF (768*512)
#define S_W1 (512*256)
#define S_W2 (256*256)
#define S_W3 (256*128)
#define S_W4 (128*128)
#define S_ALL (S_WF+S_W1+S_W2+S_W3+S_W4)

// ---------------------------------------------------------------------------
// K0: transpose all weight matrices into [k][o] layout (writes coalesced).
// ---------------------------------------------------------------------------
__global__ __launch_bounds__(256) void k_tr(
    const float* __restrict__ Wf, const float* __restrict__ W1,
    const float* __restrict__ W2, const float* __restrict__ W3,
    const float* __restrict__ W4)
{
    int i = blockIdx.x * blockDim.x + threadIdx.x;
    if (i < S_WF) { int k = i >> 9, o = i & 511; g_Wft[i] = Wf[o*768 + k]; return; }
    i -= S_WF;
    if (i < S_W1) { int k = i >> 8, o = i & 255; g_W1t[i] = W1[o*512 + k]; return; }
    i -= S_W1;
    if (i < S_W2) { int k = i >> 8, o = i & 255; g_W2t[i] = W2[o*256 + k]; return; }
    i -= S_W2;
    if (i < S_W3) { int k = i >> 7, o = i & 127; g_W3t[i] = W3[o*256 + k]; return; }
    i -= S_W3;
    if (i < S_W4) { int k = i >> 7, o = i & 127; g_W4t[i] = W4[o*128 + k]; return; }
}

// ---------------------------------------------------------------------------
// K1: fused patch-conv + MLP + prototype distances. One block = PT patches.
// Weight loads are coalesced (transposed layout); activations float4 from smem.
// ---------------------------------------------------------------------------
__global__ __launch_bounds__(256) void k_mlp(
    const float* __restrict__ x,
    const float* __restrict__ bf, const float* __restrict__ b1,
    const float* __restrict__ b2, const float* __restrict__ b3,
    const float* __restrict__ b4, const float* __restrict__ prot)
{
    extern __shared__ float sm[];
    float* sA = sm;            // PT*768 floats (24KB); reused as h2 PT*256
    float* sB = sm + PT*768;   // PT*512 (16KB);        reused as h3 src
    float* sC = sB + PT*512;   // PT*256 (8KB);         reused as h4 out

    const int tid = threadIdx.x;
    const int gp0 = blockIdx.x * PT;

    // ---- load PT patches of input (3x16x16 each) into sA
    for (int e = tid; e < PT*768; e += 256) {
        int pt = e / 768, k = e - pt*768;
        int c = k >> 8, r = (k >> 4) & 15, col = k & 15;
        int gp = gp0 + pt;
        int b = gp / NP, hw = gp - b*NP;
        int py = hw / HP, px = hw - py*HP;
        sA[e] = x[((b*3 + c)*224 + py*16 + r)*224 + px*16 + col];
    }
    __syncthreads();

    // ---- stage 0: 512 outputs (2/thread), K=768 : sA -> sB
    {
        float acc0[PT], acc1[PT];
        #pragma unroll
        for (int pt = 0; pt < PT; pt++) { acc0[pt] = 0.f; acc1[pt] = 0.f; }
        #pragma unroll 2
        for (int k = 0; k < 768; k += 4) {
            float w00 = g_Wft[(k+0)*512 + tid];
            float w01 = g_Wft[(k+1)*512 + tid];
            float w02 = g_Wft[(k+2)*512 + tid];
            float w03 = g_Wft[(k+3)*512 + tid];
            float w10 = g_Wft[(k+0)*512 + tid + 256];
            float w11 = g_Wft[(k+1)*512 + tid + 256];
            float w12 = g_Wft[(k+2)*512 + tid + 256];
            float w13 = g_Wft[(k+3)*512 + tid + 256];
            #pragma unroll
            for (int pt = 0; pt < PT; pt++) {
                float4 a = *(const float4*)&sA[pt*768 + k];
                acc0[pt] = fmaf(w00, a.x, acc0[pt]);
                acc0[pt] = fmaf(w01, a.y, acc0[pt]);
                acc0[pt] = fmaf(w02, a.z, acc0[pt]);
                acc0[pt] = fmaf(w03, a.w, acc0[pt]);
                acc1[pt] = fmaf(w10, a.x, acc1[pt]);
                acc1[pt] = fmaf(w11, a.y, acc1[pt]);
                acc1[pt] = fmaf(w12, a.z, acc1[pt]);
                acc1[pt] = fmaf(w13, a.w, acc1[pt]);
            }
        }
        float bb0 = bf[tid], bb1 = bf[tid + 256];
        #pragma unroll
        for (int pt = 0; pt < PT; pt++) {
            sB[pt*512 + tid]       = fmaxf(acc0[pt] + bb0, 0.f);
            sB[pt*512 + tid + 256] = fmaxf(acc1[pt] + bb1, 0.f);
        }
    }
    __syncthreads();

    // ---- stage 1: 256 outputs, K=512 : sB -> sC
    {
        float acc[PT];
        #pragma unroll
        for (int pt = 0; pt < PT; pt++) acc[pt] = 0.f;
        #pragma unroll 2
        for (int k = 0; k < 512; k += 4) {
            float w0 = g_W1t[(k+0)*256 + tid];
            float w1 = g_W1t[(k+1)*256 + tid];
            float w2 = g_W1t[(k+2)*256 + tid];
            float w3 = g_W1t[(k+3)*256 + tid];
            #pragma unroll
            for (int pt = 0; pt < PT; pt++) {
                float4 a = *(const float4*)&sB[pt*512 + k];
                acc[pt] = fmaf(w0, a.x, acc[pt]);
                acc[pt] = fmaf(w1, a.y, acc[pt]);
                acc[pt] = fmaf(w2, a.z, acc[pt]);
                acc[pt] = fmaf(w3, a.w, acc[pt]);
            }
        }
        float bb = b1[tid];
        #pragma unroll
        for (int pt = 0; pt < PT; pt++)
            sC[pt*256 + tid] = fmaxf(acc[pt] + bb, 0.f);
    }
    __syncthreads();

    // ---- stage 2: 256 outputs, K=256 : sC -> sA (reuse)
    {
        float acc[PT];
        #pragma unroll
        for (int pt = 0; pt < PT; pt++) acc[pt] = 0.f;
        #pragma unroll 2
        for (int k = 0; k < 256; k += 4) {
            float w0 = g_W2t[(k+0)*256 + tid];
            float w1 = g_W2t[(k+1)*256 + tid];
            float w2 = g_W2t[(k+2)*256 + tid];
            float w3 = g_W2t[(k+3)*256 + tid];
            #pragma unroll
            for (int pt = 0; pt < PT; pt++) {
                float4 a = *(const float4*)&sC[pt*256 + k];
                acc[pt] = fmaf(w0, a.x, acc[pt]);
                acc[pt] = fmaf(w1, a.y, acc[pt]);
                acc[pt] = fmaf(w2, a.z, acc[pt]);
                acc[pt] = fmaf(w3, a.w, acc[pt]);
            }
        }
        float bb = b2[tid];
        #pragma unroll
        for (int pt = 0; pt < PT; pt++)
            sA[pt*256 + tid] = fmaxf(acc[pt] + bb, 0.f);
    }
    __syncthreads();

    // ---- stage 3: 128 outputs, K=256 : sA -> sB (thread: 1 out x 4 patches)
    {
        const int o = tid & 127;
        const int half = tid >> 7;
        float acc[4] = {0.f, 0.f, 0.f, 0.f};
        #pragma unroll 2
        for (int k = 0; k < 256; k += 4) {
            float w0 = g_W3t[(k+0)*128 + o];
            float w1 = g_W3t[(k+1)*128 + o];
            float w2 = g_W3t[(k+2)*128 + o];
            float w3 = g_W3t[(k+3)*128 + o];
            #pragma unroll
            for (int j = 0; j < 4; j++) {
                float4 a = *(const float4*)&sA[(half*4 + j)*256 + k];
                acc[j] = fmaf(w0, a.x, acc[j]);
                acc[j] = fmaf(w1, a.y, acc[j]);
                acc[j] = fmaf(w2, a.z, acc[j]);
                acc[j] = fmaf(w3, a.w, acc[j]);
            }
        }
        float bb = b3[o];
        #pragma unroll
        for (int j = 0; j < 4; j++)
            sB[(half*4 + j)*128 + o] = fmaxf(acc[j] + bb, 0.f);
    }
    __syncthreads();

    // ---- stage 4: 128 outputs, K=128, sigmoid : sB -> sC
    {
        const int o = tid & 127;
        const int half = tid >> 7;
        float acc[4] = {0.f, 0.f, 0.f, 0.f};
        #pragma unroll 2
        for (int k = 0; k < 128; k += 4) {
            float w0 = g_W4t[(k+0)*128 + o];
            float w1 = g_W4t[(k+1)*128 + o];
            float w2 = g_W4t[(k+2)*128 + o];
            float w3 = g_W4t[(k+3)*128 + o];
            #pragma unroll
            for (int j = 0; j < 4; j++) {
                float4 a = *(const float4*)&sB[(half*4 + j)*128 + k];
                acc[j] = fmaf(w0, a.x, acc[j]);
                acc[j] = fmaf(w1, a.y, acc[j]);
                acc[j] = fmaf(w2, a.z, acc[j]);
                acc[j] = fmaf(w3, a.w, acc[j]);
            }
        }
        float bb = b4[o];
        #pragma unroll
        for (int j = 0; j < 4; j++) {
            float z = acc[j] + bb;
            sC[(half*4 + j)*128 + o] = 1.0f / (1.0f + expf(-z));
        }
    }
    __syncthreads();

    // ---- prototype distances + activation: 60 protos x PT patches
    for (int q = tid; q < PROTO*PT; q += 256) {
        int p  = q / PT, pt = q - p*PT;
        const float* pr = prot + p*128;
        const float* hh = sC + pt*128;
        float acc = 0.f;
        #pragma unroll 8
        for (int k = 0; k < 128; k += 4) {
            float4 h4 = *(const float4*)&hh[k];
            float4 p4 = *(const float4*)&pr[k];
            float d0 = h4.x - p4.x, d1 = h4.y - p4.y;
            float d2 = h4.z - p4.z, d3 = h4.w - p4.w;
            acc = fmaf(d0, d0, acc);
            acc = fmaf(d1, d1, acc);
            acc = fmaf(d2, d2, acc);
            acc = fmaf(d3, d3, acc);
        }
        float d = sqrtf(acc);
        float a = logf((d + 1.0f) / (d + EPSV));
        int gp = gp0 + pt;
        int b = gp / NP, hw = gp - b*NP;
        int idx = (b*PROTO + p)*NP + hw;
        g_dist[idx] = d;
        g_act[idx]  = a;
    }
}

// ---------------------------------------------------------------------------
// K2: per-(b,p) top-k smallest distances (act monotone-decreasing in d).
// One warp per task, iterative min-extract.
// ---------------------------------------------------------------------------
__global__ void k_topk(const int* __restrict__ kptr, float* __restrict__ out_mind)
{
    const int k = *kptr;
    const int warp = (blockIdx.x * blockDim.x + threadIdx.x) >> 5;
    const int lane = threadIdx.x & 31;
    if (warp >= NB*PROTO) return;

    const float* dp = g_dist + warp*NP;
    float v[7];
    #pragma unroll
    for (int j = 0; j < 7; j++) {
        int i = lane + 32*j;
        v[j] = (i < NP) ? dp[i] : 1e30f;
    }

    float sd = 0.f, sa = 0.f;
    for (int it = 0; it < k; it++) {
        float m = v[0]; int mj = 0;
        #pragma unroll
        for (int j = 1; j < 7; j++) if (v[j] < m) { m = v[j]; mj = j; }
        float bm = m; int bidx = (mj << 5) | lane;
        #pragma unroll
        for (int off = 16; off; off >>= 1) {
            float om = __shfl_xor_sync(0xffffffffu, bm, off);
            int   oi = __shfl_xor_sync(0xffffffffu, bidx, off);
            if (om < bm || (om == bm && oi < bidx)) { bm = om; bidx = oi; }
        }
        sd += bm;
        sa += logf((bm + 1.0f) / (bm + EPSV));
        if (lane == (bidx & 31)) v[bidx >> 5] = 1e30f;
    }
    if (lane == 0) {
        out_mind[warp] = sd / (float)k;
        g_pact[warp]   = sa / (float)k;
    }
}

// ---------------------------------------------------------------------------
// K3: logits[b][c] = sum_p proto_act[b][p] * last_W[c][p]
// ---------------------------------------------------------------------------
__global__ void k_logits(const float* __restrict__ lastW, float* __restrict__ out)
{
    int t = threadIdx.x;
    if (t < NB*3) {
        int b = t / 3, c = t - b*3;
        float s = 0.f;
        #pragma unroll 4
        for (int p = 0; p < PROTO; p++)
            s += g_pact[b*PROTO + p] * lastW[c*PROTO + p];
        out[t] = s;
    }
}

// ---------------------------------------------------------------------------
// K4: 16x nearest upsample of act -> 192.7 MB stores, write-bound.
// ---------------------------------------------------------------------------
__global__ __launch_bounds__(256) void k_ups(float* __restrict__ out)
{
    int i = blockIdx.x * blockDim.x + threadIdx.x;  // [0, NB*PROTO*224*14)
    int xr = i % 14;
    int t2 = i / 14;
    int y  = t2 % 224;
    int bp = t2 / 224;
    float v = g_act[bp*NP + (y >> 4)*HP + xr];
    float4 vv = make_float4(v, v, v, v);
    float4* o = (float4*)(out + ((size_t)(bp*224 + y)*224 + xr*16));
    o[0] = vv; o[1] = vv; o[2] = vv; o[3] = vv;
}

// ---------------------------------------------------------------------------
extern "C" void kernel_launch(void* const* d_in, const int* in_sizes, int n_in,
                              void* d_out, int out_size)
{
    const float* x    = (const float*)d_in[0];
    // d_in[1] = mascaras (unused by reference)
    const float* Wf   = (const float*)d_in[2];
    const float* bf   = (const float*)d_in[3];
    const float* W1   = (const float*)d_in[4];
    const float* b1   = (const float*)d_in[5];
    const float* W2   = (const float*)d_in[6];
    const float* b2   = (const float*)d_in[7];
    const float* W3   = (const float*)d_in[8];
    const float* b3   = (const float*)d_in[9];
    const float* W4   = (const float*)d_in[10];
    const float* b4   = (const float*)d_in[11];
    const float* prot = (const float*)d_in[12];
    const float* lastW= (const float*)d_in[13];
    const int*   kptr = (const int*)d_in[14];
    float* out = (float*)d_out;

    const int SMEM = PT*768*4 + PT*512*4 + PT*256*4;  // 49152 bytes
    cudaFuncSetAttribute(k_mlp, cudaFuncAttributeMaxDynamicSharedMemorySize, 64*1024);

    k_tr<<<(S_ALL + 255)/256, 256>>>(Wf, W1, W2, W3, W4);
    k_mlp<<<NBLK, 256, SMEM>>>(x, bf, b1, b2, b3, b4, prot);
    k_topk<<<(NB*PROTO*32 + 255)/256, 256>>>(kptr, out + 48);
    k_logits<<<1, 64>>>(lastW, out);
    k_ups<<<(NB*PROTO*224*14)/256, 256>>>(out + 48 + NB*PROTO);
}